// round 15
// baseline (speedup 1.0000x reference)
#include <cuda_runtime.h>
#include <cuda_bf16.h>

#define NMAX 50000
#define EMAX 800000
#define C 128
#define TOTK 20
#define NMAT 50

// ---------------- scratch (static device globals; no allocation) ----------------
__device__ int   g_degsrc[NMAX];
__device__ int   g_degdst[NMAX];
__device__ int   g_cursor[NMAX];
__device__ float g_dinv[NMAX];
__device__ int   g_rowptr[NMAX + 1];
__device__ int   g_bsum[64];
__device__ int   g_is64;
__device__ __align__(8) int2 g_epack[EMAX];
__device__ __align__(16) float g_Y[(size_t)NMAX * 512];
// persistent fp32 Chebyshev bases: [k][node][c]; slot 0 unused (x used directly)
__device__ __align__(16) float g_Tf[(size_t)TOTK * NMAX * C];
// tf32-rounded transposed weights: [mat][n][k]
__device__ __align__(16) float g_Wt[(size_t)NMAT * C * C];

__device__ __forceinline__ long long load_idx(const void* ei, int is64, size_t pos) {
    if (is64) return ((const long long*)ei)[pos];
    return (long long)((const int*)ei)[pos];
}

__device__ __forceinline__ unsigned cvt_tf32(float f) {
    unsigned r; asm("cvt.rna.tf32.f32 %0, %1;" : "=r"(r) : "f"(f)); return r;
}

// ---------------- fused init: zero counters + dtype detect (block 0) ------------
__global__ void k_init(const void* ei, int E, int N) {
    int i = blockIdx.x * blockDim.x + threadIdx.x;
    if (i < N) { g_degsrc[i] = 0; g_degdst[i] = 0; g_cursor[i] = 0; }
    if (blockIdx.x == 0) {
        __shared__ int bad;
        if (threadIdx.x == 0) bad = 0;
        __syncthreads();
        int cnt = min(E, 2048);
        for (int j = threadIdx.x; j < cnt; j += blockDim.x) {
            long long v = ((const long long*)ei)[j];
            if (v < 0 || v >= (long long)N) atomicOr(&bad, 1);
        }
        __syncthreads();
        if (threadIdx.x == 0) g_is64 = bad ? 0 : 1;
    }
}

__global__ void k_deg(const void* __restrict__ ei, int E, int N) {
    int e = blockIdx.x * blockDim.x + threadIdx.x;
    if (e < E) {
        int is64 = g_is64;
        long long s = load_idx(ei, is64, e);
        long long d = load_idx(ei, is64, (size_t)E + e);
        if (s >= 0 && s < N) atomicAdd(&g_degsrc[(int)s], 1);
        if (d >= 0 && d < N) atomicAdd(&g_degdst[(int)d], 1);
    }
}

// scan of degdst (+ fused dinv from degsrc)
__global__ void k_scan1(int N) {
    __shared__ int sh[1024];
    int tid = threadIdx.x;
    int i = blockIdx.x * 1024 + tid;
    if (i < N) {
        int d = g_degsrc[i];
        g_dinv[i] = (d > 0) ? rsqrtf((float)d) : 0.0f;
    }
    int v = (i < N) ? g_degdst[i] : 0;
    sh[tid] = v;
    __syncthreads();
    for (int off = 1; off < 1024; off <<= 1) {
        int t = (tid >= off) ? sh[tid - off] : 0;
        __syncthreads();
        sh[tid] += t;
        __syncthreads();
    }
    if (i < N) g_rowptr[i] = sh[tid] - v;
    if (tid == 1023) g_bsum[blockIdx.x] = sh[1023];
}

__global__ void k_scan2(int nb, int N) {
    if (threadIdx.x == 0 && blockIdx.x == 0) {
        int run = 0;
        for (int b = 0; b < nb; b++) { int v = g_bsum[b]; g_bsum[b] = run; run += v; }
        g_rowptr[N] = run;
    }
}

__global__ void k_scan3(int N) {
    int i = blockIdx.x * 1024 + threadIdx.x;
    if (i < N) g_rowptr[i] += g_bsum[blockIdx.x];
}

__global__ void k_scatter(const void* __restrict__ ei, int E, int N) {
    int e = blockIdx.x * blockDim.x + threadIdx.x;
    if (e < E) {
        int is64 = g_is64;
        long long sl = load_idx(ei, is64, e);
        long long dl = load_idx(ei, is64, (size_t)E + e);
        if (sl < 0 || sl >= N || dl < 0 || dl >= N) return;
        int s = (int)sl, d = (int)dl;
        float w = -g_dinv[s] * g_dinv[d] - 1.0f;
        int pos = g_rowptr[d] + atomicAdd(&g_cursor[d], 1);
        g_epack[pos] = make_int2(s, __float_as_int(w));
    }
}

// ---------------- weight prep: transpose + tf32 round ----------------
__global__ void k_wprep(const float* __restrict__ cheb_w) {
    int mat = blockIdx.x;
    const float* W = cheb_w + (size_t)mat * C * C;
    for (int idx = threadIdx.x; idx < C * C; idx += blockDim.x) {
        int kk = idx >> 7, n = idx & 127;
        unsigned r = cvt_tf32(W[idx]);
        g_Wt[(size_t)mat * C * C + (size_t)n * C + kk] = __uint_as_float(r);
    }
}

// ---------------- basis pointer: kv==0 -> x, else g_Tf slot ----------------
__device__ __forceinline__ const float* basis(int kv, const float* x, int N) {
    return (kv == 0) ? x : (g_Tf + (size_t)kv * N * C);
}

// ================ fused prop + GEMM kernel ================
// blocks [0, pgb): propagation for step kv.
// blocks [pgb, pgb+gn0): GEMM seg0 (filter gf0, kv [glo0, glo0+gcnt0), tiles gt0+i).
// blocks [pgb+gn0, +gn1): GEMM seg1.
#define SW2 36                        // 32 k-floats + 4 pad
#define CH2F (128 * SW2)              // floats per chunk buffer (18432 B)
#define FUSED_SMEM (4 * CH2F * 4)     // A0,A1,W0,W1 = 73728 B

__device__ __forceinline__ void mma_tf32(float* c, const unsigned* a, const unsigned* b) {
    asm volatile(
        "mma.sync.aligned.m16n8k8.row.col.f32.tf32.tf32.f32 "
        "{%0,%1,%2,%3}, {%4,%5,%6,%7}, {%8,%9}, {%0,%1,%2,%3};\n"
        : "+f"(c[0]), "+f"(c[1]), "+f"(c[2]), "+f"(c[3])
        : "r"(a[0]), "r"(a[1]), "r"(a[2]), "r"(a[3]), "r"(b[0]), "r"(b[1]));
}

__device__ __forceinline__ void cpa16(unsigned saddr, const void* g, int sz) {
    asm volatile("cp.async.cg.shared.global [%0], [%1], 16, %2;\n"
                 :: "r"(saddr), "l"(g), "r"(sz));
}

__device__ __forceinline__ void load_chunk2(unsigned sbase, int buf, int kv, int mat,
                                            int ch, int tilebase, int N,
                                            const float* __restrict__ x) {
    int t = threadIdx.x;
    const float* A = basis(kv, x, N) + ch * 32;
    const float* W = g_Wt + (size_t)mat * C * C + ch * 32;
    unsigned ab = sbase + (unsigned)buf * (CH2F * 4);
    unsigned wb = sbase + (unsigned)(2 + buf) * (CH2F * 4);
#pragma unroll
    for (int j = 0; j < 4; ++j) {
        int idx = t + j * 256;
        int row = idx >> 3, seg = idx & 7;           // 8 segs of 4 floats = 32
        unsigned so = (unsigned)(row * SW2 + seg * 4) * 4;
        int grow = tilebase + row;
        if (grow > N - 1) grow = N - 1;
        cpa16(ab + so, A + (size_t)grow * C + seg * 4, 16);
        cpa16(wb + so, W + (size_t)row * C + seg * 4, 16);
    }
}

extern __shared__ __align__(16) float sm_f[];

__global__ void __launch_bounds__(256)
k_fused(int kv, const float* __restrict__ x, float alpha, float beta, int N, int pgb,
        int gf0, int glo0, int gcnt0, int gacc0, int gt0, int gn0,
        int gf1, int glo1, int gcnt1, int gacc1, int gt1, int gn1,
        const float* __restrict__ cheb_b) {
    if ((int)blockIdx.x < pgb) {
        // ---------- propagation branch ----------
        const float4* Tin  = (const float4*)basis(kv - 1, x, N);
        const float4* Tsub = (const float4*)basis(kv >= 2 ? kv - 2 : 0, x, N);
        float4*       Tout = (float4*)(g_Tf + (size_t)kv * N * C);

        int node = (blockIdx.x * blockDim.x + threadIdx.x) >> 5;
        if (node >= N) return;
        int lane = threadIdx.x & 31;

        int beg = g_rowptr[node], end = g_rowptr[node + 1];
        float4 acc = make_float4(0.f, 0.f, 0.f, 0.f);

        int j = beg;
        for (; j + 4 <= end; j += 4) {
            int2 e0 = g_epack[j];
            int2 e1 = g_epack[j + 1];
            int2 e2 = g_epack[j + 2];
            int2 e3 = g_epack[j + 3];
            float4 a0 = Tin[(size_t)e0.x * 32 + lane];
            float4 a1 = Tin[(size_t)e1.x * 32 + lane];
            float4 a2 = Tin[(size_t)e2.x * 32 + lane];
            float4 a3 = Tin[(size_t)e3.x * 32 + lane];
            float w0 = __int_as_float(e0.y), w1 = __int_as_float(e1.y);
            float w2 = __int_as_float(e2.y), w3 = __int_as_float(e3.y);
            acc.x += w0 * a0.x; acc.y += w0 * a0.y; acc.z += w0 * a0.z; acc.w += w0 * a0.w;
            acc.x += w1 * a1.x; acc.y += w1 * a1.y; acc.z += w1 * a1.z; acc.w += w1 * a1.w;
            acc.x += w2 * a2.x; acc.y += w2 * a2.y; acc.z += w2 * a2.z; acc.w += w2 * a2.w;
            acc.x += w3 * a3.x; acc.y += w3 * a3.y; acc.z += w3 * a3.z; acc.w += w3 * a3.w;
        }
        for (; j < end; ++j) {
            int2 e = g_epack[j];
            float w = __int_as_float(e.y);
            float4 a = Tin[(size_t)e.x * 32 + lane];
            acc.x += w * a.x; acc.y += w * a.y; acc.z += w * a.z; acc.w += w * a.w;
        }

        float4 sv = Tsub[(size_t)node * 32 + lane];
        float4 v;
        v.x = alpha * acc.x + beta * sv.x;
        v.y = alpha * acc.y + beta * sv.y;
        v.z = alpha * acc.z + beta * sv.z;
        v.w = alpha * acc.w + beta * sv.w;
        Tout[(size_t)node * 32 + lane] = v;
        return;
    }

    // ---------- GEMM branch ----------
    int gb = (int)blockIdx.x - pgb;
    int f, klo, kcnt, acm, tile;
    if (gb < gn0) { f = gf0; klo = glo0; kcnt = gcnt0; acm = gacc0; tile = gt0 + gb; }
    else { gb -= gn0; if (gb >= gn1) return;
           f = gf1; klo = glo1; kcnt = gcnt1; acm = gacc1; tile = gt1 + gb; }

    int tilebase = tile * 128;
    int off = 5 * f * (f + 1) / 2;
    int NC = kcnt * 4;                  // 4 chunks of 32 k per kv

    unsigned sbase = (unsigned)__cvta_generic_to_shared(sm_f);
    int t = threadIdx.x;
    int lane = t & 31, w = t >> 5;
    int warp_m = w & 3, warp_n = w >> 2;
    int g = lane >> 2, tig = lane & 3;

    float acc[2][8][4];
#pragma unroll
    for (int mt = 0; mt < 2; ++mt)
#pragma unroll
        for (int nt = 0; nt < 8; ++nt)
#pragma unroll
            for (int r = 0; r < 4; ++r) acc[mt][nt][r] = 0.0f;

    load_chunk2(sbase, 0, klo, off + klo, 0, tilebase, N, x);
    asm volatile("cp.async.commit_group;\n" ::: "memory");

    for (int i = 0; i < NC; ++i) {
        if (i + 1 < NC) {
            int kvn = klo + ((i + 1) >> 2), ch = (i + 1) & 3;
            load_chunk2(sbase, (i + 1) & 1, kvn, off + kvn, ch, tilebase, N, x);
        }
        asm volatile("cp.async.commit_group;\n" ::: "memory");
        if (i + 1 < NC) asm volatile("cp.async.wait_group 1;\n" ::: "memory");
        else            asm volatile("cp.async.wait_group 0;\n" ::: "memory");
        __syncthreads();

        const float* As = sm_f + (i & 1) * CH2F;
        const float* Ws = sm_f + (2 + (i & 1)) * CH2F;

#pragma unroll
        for (int ks = 0; ks < 4; ++ks) {
            unsigned a[2][4], b[8][2];
#pragma unroll
            for (int mt = 0; mt < 2; ++mt) {
                int R = warp_m * 32 + mt * 16;
                int kc = ks * 8 + tig;
                a[mt][0] = cvt_tf32(As[(R + g)     * SW2 + kc]);
                a[mt][1] = cvt_tf32(As[(R + 8 + g) * SW2 + kc]);
                a[mt][2] = cvt_tf32(As[(R + g)     * SW2 + kc + 4]);
                a[mt][3] = cvt_tf32(As[(R + 8 + g) * SW2 + kc + 4]);
            }
#pragma unroll
            for (int nt = 0; nt < 8; ++nt) {
                int n = warp_n * 64 + nt * 8 + g;
                int kc = ks * 8 + tig;
                b[nt][0] = __float_as_uint(Ws[n * SW2 + kc]);
                b[nt][1] = __float_as_uint(Ws[n * SW2 + kc + 4]);
            }
#pragma unroll
            for (int mt = 0; mt < 2; ++mt)
#pragma unroll
                for (int nt = 0; nt < 8; ++nt)
                    mma_tf32(acc[mt][nt], a[mt], b[nt]);
        }
        __syncthreads();
    }

#pragma unroll
    for (int mt = 0; mt < 2; ++mt) {
        int r0 = tilebase + warp_m * 32 + mt * 16 + g;
#pragma unroll
        for (int nt = 0; nt < 8; ++nt) {
            int col = warp_n * 64 + nt * 8 + tig * 2;
            size_t gc = (size_t)f * 128 + col;
            if (acm) {
                if (r0 < N) {
                    float2* yp = (float2*)&g_Y[(size_t)r0 * 512 + gc];
                    float2 y = *yp;
                    y.x += acc[mt][nt][0]; y.y += acc[mt][nt][1];
                    *yp = y;
                }
                if (r0 + 8 < N) {
                    float2* yp = (float2*)&g_Y[(size_t)(r0 + 8) * 512 + gc];
                    float2 y = *yp;
                    y.x += acc[mt][nt][2]; y.y += acc[mt][nt][3];
                    *yp = y;
                }
            } else {
                float b0v = cheb_b[f * 128 + col];
                float b1v = cheb_b[f * 128 + col + 1];
                if (r0 < N) {
                    float2 v = make_float2(acc[mt][nt][0] + b0v, acc[mt][nt][1] + b1v);
                    *(float2*)&g_Y[(size_t)r0 * 512 + gc] = v;
                }
                if (r0 + 8 < N) {
                    float2 v = make_float2(acc[mt][nt][2] + b0v, acc[mt][nt][3] + b1v);
                    *(float2*)&g_Y[(size_t)(r0 + 8) * 512 + gc] = v;
                }
            }
        }
    }
}

// ---------------- attention softmax + combine + layernorm (warp-per-node) -------
__global__ void __launch_bounds__(256)
k_final(const float* __restrict__ attn_w, const float* __restrict__ attn_b,
        const float* __restrict__ ln_g, const float* __restrict__ ln_b,
        float* __restrict__ out, int N) {
    int node = (blockIdx.x * blockDim.x + threadIdx.x) >> 5;
    if (node >= N) return;
    int lane = threadIdx.x & 31;

    const float4* yr = (const float4*)(g_Y + (size_t)node * 512);
    const float4* aw = (const float4*)attn_w;

    float4 v[4];
    float l0 = 0.f, l1 = 0.f, l2 = 0.f, l3 = 0.f;
#pragma unroll
    for (int f = 0; f < 4; ++f) {
        v[f] = yr[f * 32 + lane];
        int jb = f * 128 + lane * 4;
        float4 a0 = aw[jb], a1 = aw[jb + 1], a2 = aw[jb + 2], a3 = aw[jb + 3];
        l0 += v[f].x * a0.x + v[f].y * a1.x + v[f].z * a2.x + v[f].w * a3.x;
        l1 += v[f].x * a0.y + v[f].y * a1.y + v[f].z * a2.y + v[f].w * a3.y;
        l2 += v[f].x * a0.z + v[f].y * a1.z + v[f].z * a2.z + v[f].w * a3.z;
        l3 += v[f].x * a0.w + v[f].y * a1.w + v[f].z * a2.w + v[f].w * a3.w;
    }
#pragma unroll
    for (int o = 16; o > 0; o >>= 1) {
        l0 += __shfl_xor_sync(0xffffffffu, l0, o);
        l1 += __shfl_xor_sync(0xffffffffu, l1, o);
        l2 += __shfl_xor_sync(0xffffffffu, l2, o);
        l3 += __shfl_xor_sync(0xffffffffu, l3, o);
    }
    l0 += attn_b[0]; l1 += attn_b[1]; l2 += attn_b[2]; l3 += attn_b[3];
    float m = fmaxf(fmaxf(l0, l1), fmaxf(l2, l3));
    float e0 = expf(l0 - m), e1 = expf(l1 - m), e2 = expf(l2 - m), e3 = expf(l3 - m);
    float s = e0 + e1 + e2 + e3;
    float a0 = e0 / s, a1 = e1 / s, a2 = e2 / s, a3 = e3 / s;

    float4 cmb;
    cmb.x = a0 * v[0].x + a1 * v[1].x + a2 * v[2].x + a3 * v[3].x;
    cmb.y = a0 * v[0].y + a1 * v[1].y + a2 * v[2].y + a3 * v[3].y;
    cmb.z = a0 * v[0].z + a1 * v[1].z + a2 * v[2].z + a3 * v[3].z;
    cmb.w = a0 * v[0].w + a1 * v[1].w + a2 * v[2].w + a3 * v[3].w;

    float ssum = cmb.x + cmb.y + cmb.z + cmb.w;
#pragma unroll
    for (int o = 16; o > 0; o >>= 1) ssum += __shfl_xor_sync(0xffffffffu, ssum, o);
    float mu = ssum * (1.0f / 128.0f);

    float4 d = make_float4(cmb.x - mu, cmb.y - mu, cmb.z - mu, cmb.w - mu);
    float vs = d.x * d.x + d.y * d.y + d.z * d.z + d.w * d.w;
#pragma unroll
    for (int o = 16; o > 0; o >>= 1) vs += __shfl_xor_sync(0xffffffffu, vs, o);
    float var = vs * (1.0f / 128.0f);
    float inv = rsqrtf(var + 1e-5f);

    float4 gg = ((const float4*)ln_g)[lane];
    float4 bb = ((const float4*)ln_b)[lane];
    float4 o4;
    o4.x = d.x * inv * gg.x + bb.x;
    o4.y = d.y * inv * gg.y + bb.y;
    o4.z = d.z * inv * gg.z + bb.z;
    o4.w = d.w * inv * gg.w + bb.w;
    ((float4*)out)[(size_t)node * 32 + lane] = o4;
}

// ---------------- host ----------------
extern "C" void kernel_launch(void* const* d_in, const int* in_sizes, int n_in,
                              void* d_out, int out_size) {
    const float* x      = (const float*)d_in[0];
    const void*  ei     = d_in[1];
    const float* cheb_w = (const float*)d_in[2];
    const float* cheb_b = (const float*)d_in[3];
    const float* attn_w = (const float*)d_in[4];
    const float* attn_b = (const float*)d_in[5];
    const float* ln_g   = (const float*)d_in[6];
    const float* ln_b   = (const float*)d_in[7];
    float*       out    = (float*)d_out;

    int N = in_sizes[0] / 128;
    int E = in_sizes[1] / 2;
    if (N > NMAX) N = NMAX;
    if (E > EMAX) E = EMAX;

    static int inited = 0;
    if (!inited) {
        cudaFuncSetAttribute(k_fused, cudaFuncAttributeMaxDynamicSharedMemorySize,
                             FUSED_SMEM);
        inited = 1;
    }

    int tiles = (N + 127) / 128;        // 391
    int pgrid = (N * 32 + 255) / 256;   // prop blocks
    int slice = (tiles + 4) / 5;        // tiles per launch slice

    // setup (all default stream)
    k_wprep<<<NMAT, 256>>>(cheb_w);
    k_init<<<(N + 255) / 256, 256>>>(ei, E, N);
    k_deg<<<(E + 255) / 256, 256>>>(ei, E, N);
    int nb = (N + 1023) / 1024;
    k_scan1<<<nb, 1024>>>(N);
    k_scan2<<<1, 32>>>(nb, N);
    k_scan3<<<nb, 1024>>>(N);
    k_scatter<<<(E + 255) / 256, 256>>>(ei, E, N);

    // fused prop + sliced GEMM; everything default-stream ordered
    auto launch = [&](int kv, float alpha, float beta,
                      int f0, int lo0, int c0, int a0, int t0, int n0,
                      int f1, int lo1, int c1, int a1, int t1, int n1) {
        k_fused<<<pgrid + n0 + n1, 256, FUSED_SMEM>>>(
            kv, x, alpha, beta, N, pgrid,
            f0, lo0, c0, a0, t0, n0,
            f1, lo1, c1, a1, t1, n1, cheb_b);
    };

    // props 1..4: pure
    launch(1, 1.0f, 0.0f, 0,0,0,0,0,0, 0,0,0,0,0,0);
    for (int k = 2; k <= 4; ++k)
        launch(k, 2.0f, -1.0f, 0,0,0,0,0,0, 0,0,0,0,0,0);

    // props 5..9: + f0 (kv0-4) tile slices
    for (int k = 5; k <= 9; ++k) {
        int st = (k - 5) * slice;
        int cn = (st < tiles) ? ((tiles - st < slice) ? (tiles - st) : slice) : 0;
        launch(k, 2.0f, -1.0f, 0, 0, 5, 0, st, cn, 0,0,0,0,0,0);
    }

    // props 10..14: + f1 (kv0-9) slices
    for (int k = 10; k <= 14; ++k) {
        int st = (k - 10) * slice;
        int cn = (st < tiles) ? ((tiles - st < slice) ? (tiles - st) : slice) : 0;
        launch(k, 2.0f, -1.0f, 1, 0, 10, 0, st, cn, 0,0,0,0,0,0);
    }

    // props 15..19: + f2 (kv0-14) and f3 part 1 (kv0-14) slices
    for (int k = 15; k <= 19; ++k) {
        int st = (k - 15) * slice;
        int cn = (st < tiles) ? ((tiles - st < slice) ? (tiles - st) : slice) : 0;
        launch(k, 2.0f, -1.0f, 2, 0, 15, 0, st, cn, 3, 0, 15, 0, st, cn);
    }

    // tail: f3 kv15-19 (accumulate into Y); no prop blocks
    k_fused<<<tiles, 256, FUSED_SMEM>>>(
        1, x, 0.0f, 0.0f, N, 0,
        3, 15, 5, 1, 0, tiles,
        0, 0, 0, 0, 0, 0, cheb_b);

    k_final<<<pgrid, 256>>>(attn_w, attn_b, ln_g, ln_b, out, N);
}

// round 16
// speedup vs baseline: 2.0724x; 2.0724x over previous
#include <cuda_runtime.h>
#include <cuda_bf16.h>

#define NMAX 50000
#define EMAX 800000
#define C 128
#define TOTK 20
#define NMAT 50

// ---------------- scratch (static device globals; no allocation) ----------------
__device__ int   g_degsrc[NMAX];
__device__ int   g_degdst[NMAX];
__device__ int   g_cursor[NMAX];
__device__ float g_dinv[NMAX];
__device__ int   g_rowptr[NMAX + 1];
__device__ int   g_bsum[64];
__device__ int   g_is64;
__device__ __align__(8) int2 g_epack[EMAX];
__device__ __align__(16) float g_Y[(size_t)NMAX * 512];
// persistent fp32 Chebyshev bases: [k][node][c]; slot 0 unused (x used directly)
__device__ __align__(16) float g_Tf[(size_t)TOTK * NMAX * C];
// tf32-rounded transposed weights: [mat][n][k]
__device__ __align__(16) float g_Wt[(size_t)NMAT * C * C];

__device__ __forceinline__ long long load_idx(const void* ei, int is64, size_t pos) {
    if (is64) return ((const long long*)ei)[pos];
    return (long long)((const int*)ei)[pos];
}

__device__ __forceinline__ unsigned cvt_tf32(float f) {
    unsigned r; asm("cvt.rna.tf32.f32 %0, %1;" : "=r"(r) : "f"(f)); return r;
}

// ---------------- fused init: zero counters + dtype detect (block 0) ------------
__global__ void k_init(const void* ei, int E, int N) {
    int i = blockIdx.x * blockDim.x + threadIdx.x;
    if (i < N) { g_degsrc[i] = 0; g_degdst[i] = 0; g_cursor[i] = 0; }
    if (blockIdx.x == 0) {
        __shared__ int bad;
        if (threadIdx.x == 0) bad = 0;
        __syncthreads();
        int cnt = min(E, 2048);
        for (int j = threadIdx.x; j < cnt; j += blockDim.x) {
            long long v = ((const long long*)ei)[j];
            if (v < 0 || v >= (long long)N) atomicOr(&bad, 1);
        }
        __syncthreads();
        if (threadIdx.x == 0) g_is64 = bad ? 0 : 1;
    }
}

__global__ void k_deg(const void* __restrict__ ei, int E, int N) {
    int e = blockIdx.x * blockDim.x + threadIdx.x;
    if (e < E) {
        int is64 = g_is64;
        long long s = load_idx(ei, is64, e);
        long long d = load_idx(ei, is64, (size_t)E + e);
        if (s >= 0 && s < N) atomicAdd(&g_degsrc[(int)s], 1);
        if (d >= 0 && d < N) atomicAdd(&g_degdst[(int)d], 1);
    }
}

// scan of degdst (+ fused dinv from degsrc)
__global__ void k_scan1(int N) {
    __shared__ int sh[1024];
    int tid = threadIdx.x;
    int i = blockIdx.x * 1024 + tid;
    if (i < N) {
        int d = g_degsrc[i];
        g_dinv[i] = (d > 0) ? rsqrtf((float)d) : 0.0f;
    }
    int v = (i < N) ? g_degdst[i] : 0;
    sh[tid] = v;
    __syncthreads();
    for (int off = 1; off < 1024; off <<= 1) {
        int t = (tid >= off) ? sh[tid - off] : 0;
        __syncthreads();
        sh[tid] += t;
        __syncthreads();
    }
    if (i < N) g_rowptr[i] = sh[tid] - v;
    if (tid == 1023) g_bsum[blockIdx.x] = sh[1023];
}

__global__ void k_scan2(int nb, int N) {
    if (threadIdx.x == 0 && blockIdx.x == 0) {
        int run = 0;
        for (int b = 0; b < nb; b++) { int v = g_bsum[b]; g_bsum[b] = run; run += v; }
        g_rowptr[N] = run;
    }
}

__global__ void k_scan3(int N) {
    int i = blockIdx.x * 1024 + threadIdx.x;
    if (i < N) g_rowptr[i] += g_bsum[blockIdx.x];
}

__global__ void k_scatter(const void* __restrict__ ei, int E, int N) {
    int e = blockIdx.x * blockDim.x + threadIdx.x;
    if (e < E) {
        int is64 = g_is64;
        long long sl = load_idx(ei, is64, e);
        long long dl = load_idx(ei, is64, (size_t)E + e);
        if (sl < 0 || sl >= N || dl < 0 || dl >= N) return;
        int s = (int)sl, d = (int)dl;
        float w = -g_dinv[s] * g_dinv[d] - 1.0f;
        int pos = g_rowptr[d] + atomicAdd(&g_cursor[d], 1);
        g_epack[pos] = make_int2(s, __float_as_int(w));
    }
}

// ---------------- weight prep: transpose + tf32 round ----------------
__global__ void k_wprep(const float* __restrict__ cheb_w) {
    int mat = blockIdx.x;
    const float* W = cheb_w + (size_t)mat * C * C;
    for (int idx = threadIdx.x; idx < C * C; idx += blockDim.x) {
        int kk = idx >> 7, n = idx & 127;
        unsigned r = cvt_tf32(W[idx]);
        g_Wt[(size_t)mat * C * C + (size_t)n * C + kk] = __uint_as_float(r);
    }
}

// ---------------- basis pointer: kv==0 -> x, else g_Tf slot ----------------
__device__ __forceinline__ const float* basis(int kv, const float* x, int N) {
    return (kv == 0) ? x : (g_Tf + (size_t)kv * N * C);
}

// ---------------- propagation: warp-per-node, float4, 4-edge unroll ------------
__global__ void __launch_bounds__(256)
k_prop(int kv, const float* __restrict__ x, float alpha, float beta, int N) {
    const float4* Tin  = (const float4*)basis(kv - 1, x, N);
    const float4* Tsub = (const float4*)basis(kv >= 2 ? kv - 2 : 0, x, N);
    float4*       Tout = (float4*)(g_Tf + (size_t)kv * N * C);

    int node = (blockIdx.x * blockDim.x + threadIdx.x) >> 5;
    if (node >= N) return;
    int lane = threadIdx.x & 31;

    int beg = g_rowptr[node], end = g_rowptr[node + 1];
    float4 acc = make_float4(0.f, 0.f, 0.f, 0.f);

    int j = beg;
    for (; j + 4 <= end; j += 4) {
        int2 e0 = g_epack[j];
        int2 e1 = g_epack[j + 1];
        int2 e2 = g_epack[j + 2];
        int2 e3 = g_epack[j + 3];
        float4 a0 = Tin[(size_t)e0.x * 32 + lane];
        float4 a1 = Tin[(size_t)e1.x * 32 + lane];
        float4 a2 = Tin[(size_t)e2.x * 32 + lane];
        float4 a3 = Tin[(size_t)e3.x * 32 + lane];
        float w0 = __int_as_float(e0.y), w1 = __int_as_float(e1.y);
        float w2 = __int_as_float(e2.y), w3 = __int_as_float(e3.y);
        acc.x += w0 * a0.x; acc.y += w0 * a0.y; acc.z += w0 * a0.z; acc.w += w0 * a0.w;
        acc.x += w1 * a1.x; acc.y += w1 * a1.y; acc.z += w1 * a1.z; acc.w += w1 * a1.w;
        acc.x += w2 * a2.x; acc.y += w2 * a2.y; acc.z += w2 * a2.z; acc.w += w2 * a2.w;
        acc.x += w3 * a3.x; acc.y += w3 * a3.y; acc.z += w3 * a3.z; acc.w += w3 * a3.w;
    }
    for (; j < end; ++j) {
        int2 e = g_epack[j];
        float w = __int_as_float(e.y);
        float4 a = Tin[(size_t)e.x * 32 + lane];
        acc.x += w * a.x; acc.y += w * a.y; acc.z += w * a.z; acc.w += w * a.w;
    }

    float4 sv = Tsub[(size_t)node * 32 + lane];
    float4 v;
    v.x = alpha * acc.x + beta * sv.x;
    v.y = alpha * acc.y + beta * sv.y;
    v.z = alpha * acc.z + beta * sv.z;
    v.w = alpha * acc.w + beta * sv.w;
    Tout[(size_t)node * 32 + lane] = v;
}

// ---------------- tf32 tensor-core GEMM, M=256 tiles (halved W traffic) ---------
#define SW2 36                         // 32 k-floats + 4 pad
#define A_CH (256 * SW2)               // A chunk: 256 rows x 32 k (36864 B)
#define W_CH (128 * SW2)               // W chunk: 128 n x 32 k (18432 B)
#define GEMM_SMEM_B ((2 * A_CH + 2 * W_CH) * 4)   // 110592 B

__device__ __forceinline__ void mma_tf32(float* c, const unsigned* a, const unsigned* b) {
    asm volatile(
        "mma.sync.aligned.m16n8k8.row.col.f32.tf32.tf32.f32 "
        "{%0,%1,%2,%3}, {%4,%5,%6,%7}, {%8,%9}, {%0,%1,%2,%3};\n"
        : "+f"(c[0]), "+f"(c[1]), "+f"(c[2]), "+f"(c[3])
        : "r"(a[0]), "r"(a[1]), "r"(a[2]), "r"(a[3]), "r"(b[0]), "r"(b[1]));
}

__device__ __forceinline__ void cpa16(unsigned saddr, const void* g, int sz) {
    asm volatile("cp.async.cg.shared.global [%0], [%1], 16, %2;\n"
                 :: "r"(saddr), "l"(g), "r"(sz));
}

// load one (kv, 32k-chunk ch) into buffer buf: A 256 rows + W 128 n-rows
__device__ __forceinline__ void gemm_load_chunk(unsigned sbase, int buf, int kv, int mat,
                                                int ch, int tilebase, int N,
                                                const float* __restrict__ x) {
    int t = threadIdx.x;
    const float* A = basis(kv, x, N) + ch * 32;
    const float* W = g_Wt + (size_t)mat * C * C + ch * 32;
    unsigned ab = sbase + (unsigned)buf * (A_CH * 4);
    unsigned wb = sbase + (unsigned)(2 * A_CH + buf * W_CH) * 4;
    // A: 256 rows x 8 segs = 2048 float4 -> 8 iters
#pragma unroll
    for (int j = 0; j < 8; ++j) {
        int idx = t + j * 256;
        int row = idx >> 3, seg = idx & 7;
        unsigned so = (unsigned)(row * SW2 + seg * 4) * 4;
        int grow = tilebase + row;
        if (grow > N - 1) grow = N - 1;
        cpa16(ab + so, A + (size_t)grow * C + seg * 4, 16);
    }
    // W: 128 rows x 8 segs = 1024 float4 -> 4 iters
#pragma unroll
    for (int j = 0; j < 4; ++j) {
        int idx = t + j * 256;
        int row = idx >> 3, seg = idx & 7;
        unsigned so = (unsigned)(row * SW2 + seg * 4) * 4;
        cpa16(wb + so, W + (size_t)row * C + seg * 4, 16);
    }
}

extern __shared__ __align__(16) float sm_f[];

__global__ void __launch_bounds__(256)
k_gemm_all(const float* __restrict__ cheb_b, const float* __restrict__ x,
           int N, int f, int kv_lo, int kv_cnt, int accum) {
    int tilebase = blockIdx.x * 256;
    int off = 5 * f * (f + 1) / 2;
    int NC = kv_cnt * 4;                 // 4 chunks of 32 k per kv

    unsigned sbase = (unsigned)__cvta_generic_to_shared(sm_f);
    int t = threadIdx.x;
    int lane = t & 31, w = t >> 5;       // 8 warps: warp w -> rows [w*32, w*32+32)
    int g = lane >> 2, tig = lane & 3;

    float acc[2][16][4];
#pragma unroll
    for (int mt = 0; mt < 2; ++mt)
#pragma unroll
        for (int nt = 0; nt < 16; ++nt)
#pragma unroll
            for (int r = 0; r < 4; ++r) acc[mt][nt][r] = 0.0f;

    gemm_load_chunk(sbase, 0, kv_lo, off + kv_lo, 0, tilebase, N, x);
    asm volatile("cp.async.commit_group;\n" ::: "memory");

    for (int i = 0; i < NC; ++i) {
        if (i + 1 < NC) {
            int kv = kv_lo + ((i + 1) >> 2), ch = (i + 1) & 3;
            gemm_load_chunk(sbase, (i + 1) & 1, kv, off + kv, ch, tilebase, N, x);
        }
        asm volatile("cp.async.commit_group;\n" ::: "memory");
        if (i + 1 < NC) asm volatile("cp.async.wait_group 1;\n" ::: "memory");
        else            asm volatile("cp.async.wait_group 0;\n" ::: "memory");
        __syncthreads();

        const float* As = sm_f + (i & 1) * A_CH;
        const float* Ws = sm_f + 2 * A_CH + (i & 1) * W_CH;

#pragma unroll
        for (int ks = 0; ks < 4; ++ks) {
            int kc = ks * 8 + tig;
            unsigned a[2][4];
#pragma unroll
            for (int mt = 0; mt < 2; ++mt) {
                int R = w * 32 + mt * 16;
                a[mt][0] = cvt_tf32(As[(R + g)     * SW2 + kc]);
                a[mt][1] = cvt_tf32(As[(R + 8 + g) * SW2 + kc]);
                a[mt][2] = cvt_tf32(As[(R + g)     * SW2 + kc + 4]);
                a[mt][3] = cvt_tf32(As[(R + 8 + g) * SW2 + kc + 4]);
            }
#pragma unroll
            for (int nt = 0; nt < 16; ++nt) {
                int n = nt * 8 + g;
                unsigned b[2];
                b[0] = __float_as_uint(Ws[n * SW2 + kc]);
                b[1] = __float_as_uint(Ws[n * SW2 + kc + 4]);
                mma_tf32(acc[0][nt], a[0], b);
                mma_tf32(acc[1][nt], a[1], b);
            }
        }
        __syncthreads();
    }

#pragma unroll
    for (int mt = 0; mt < 2; ++mt) {
        int r0 = tilebase + w * 32 + mt * 16 + g;
#pragma unroll
        for (int nt = 0; nt < 16; ++nt) {
            int col = nt * 8 + tig * 2;
            size_t gc = (size_t)f * 128 + col;
            if (accum) {
                if (r0 < N) {
                    float2* yp = (float2*)&g_Y[(size_t)r0 * 512 + gc];
                    float2 y = *yp;
                    y.x += acc[mt][nt][0]; y.y += acc[mt][nt][1];
                    *yp = y;
                }
                if (r0 + 8 < N) {
                    float2* yp = (float2*)&g_Y[(size_t)(r0 + 8) * 512 + gc];
                    float2 y = *yp;
                    y.x += acc[mt][nt][2]; y.y += acc[mt][nt][3];
                    *yp = y;
                }
            } else {
                float b0v = cheb_b[f * 128 + col];
                float b1v = cheb_b[f * 128 + col + 1];
                if (r0 < N) {
                    float2 v = make_float2(acc[mt][nt][0] + b0v, acc[mt][nt][1] + b1v);
                    *(float2*)&g_Y[(size_t)r0 * 512 + gc] = v;
                }
                if (r0 + 8 < N) {
                    float2 v = make_float2(acc[mt][nt][2] + b0v, acc[mt][nt][3] + b1v);
                    *(float2*)&g_Y[(size_t)(r0 + 8) * 512 + gc] = v;
                }
            }
        }
    }
}

// ---------------- attention softmax + combine + layernorm (warp-per-node) -------
__global__ void __launch_bounds__(256)
k_final(const float* __restrict__ attn_w, const float* __restrict__ attn_b,
        const float* __restrict__ ln_g, const float* __restrict__ ln_b,
        float* __restrict__ out, int N) {
    int node = (blockIdx.x * blockDim.x + threadIdx.x) >> 5;
    if (node >= N) return;
    int lane = threadIdx.x & 31;

    const float4* yr = (const float4*)(g_Y + (size_t)node * 512);
    const float4* aw = (const float4*)attn_w;

    float4 v[4];
    float l0 = 0.f, l1 = 0.f, l2 = 0.f, l3 = 0.f;
#pragma unroll
    for (int f = 0; f < 4; ++f) {
        v[f] = yr[f * 32 + lane];
        int jb = f * 128 + lane * 4;
        float4 a0 = aw[jb], a1 = aw[jb + 1], a2 = aw[jb + 2], a3 = aw[jb + 3];
        l0 += v[f].x * a0.x + v[f].y * a1.x + v[f].z * a2.x + v[f].w * a3.x;
        l1 += v[f].x * a0.y + v[f].y * a1.y + v[f].z * a2.y + v[f].w * a3.y;
        l2 += v[f].x * a0.z + v[f].y * a1.z + v[f].z * a2.z + v[f].w * a3.z;
        l3 += v[f].x * a0.w + v[f].y * a1.w + v[f].z * a2.w + v[f].w * a3.w;
    }
#pragma unroll
    for (int o = 16; o > 0; o >>= 1) {
        l0 += __shfl_xor_sync(0xffffffffu, l0, o);
        l1 += __shfl_xor_sync(0xffffffffu, l1, o);
        l2 += __shfl_xor_sync(0xffffffffu, l2, o);
        l3 += __shfl_xor_sync(0xffffffffu, l3, o);
    }
    l0 += attn_b[0]; l1 += attn_b[1]; l2 += attn_b[2]; l3 += attn_b[3];
    float m = fmaxf(fmaxf(l0, l1), fmaxf(l2, l3));
    float e0 = expf(l0 - m), e1 = expf(l1 - m), e2 = expf(l2 - m), e3 = expf(l3 - m);
    float s = e0 + e1 + e2 + e3;
    float a0 = e0 / s, a1 = e1 / s, a2 = e2 / s, a3 = e3 / s;

    float4 cmb;
    cmb.x = a0 * v[0].x + a1 * v[1].x + a2 * v[2].x + a3 * v[3].x;
    cmb.y = a0 * v[0].y + a1 * v[1].y + a2 * v[2].y + a3 * v[3].y;
    cmb.z = a0 * v[0].z + a1 * v[1].z + a2 * v[2].z + a3 * v[3].z;
    cmb.w = a0 * v[0].w + a1 * v[1].w + a2 * v[2].w + a3 * v[3].w;

    float ssum = cmb.x + cmb.y + cmb.z + cmb.w;
#pragma unroll
    for (int o = 16; o > 0; o >>= 1) ssum += __shfl_xor_sync(0xffffffffu, ssum, o);
    float mu = ssum * (1.0f / 128.0f);

    float4 d = make_float4(cmb.x - mu, cmb.y - mu, cmb.z - mu, cmb.w - mu);
    float vs = d.x * d.x + d.y * d.y + d.z * d.z + d.w * d.w;
#pragma unroll
    for (int o = 16; o > 0; o >>= 1) vs += __shfl_xor_sync(0xffffffffu, vs, o);
    float var = vs * (1.0f / 128.0f);
    float inv = rsqrtf(var + 1e-5f);

    float4 gg = ((const float4*)ln_g)[lane];
    float4 bb = ((const float4*)ln_b)[lane];
    float4 o4;
    o4.x = d.x * inv * gg.x + bb.x;
    o4.y = d.y * inv * gg.y + bb.y;
    o4.z = d.z * inv * gg.z + bb.z;
    o4.w = d.w * inv * gg.w + bb.w;
    ((float4*)out)[(size_t)node * 32 + lane] = o4;
}

// ---------------- host ----------------
extern "C" void kernel_launch(void* const* d_in, const int* in_sizes, int n_in,
                              void* d_out, int out_size) {
    const float* x      = (const float*)d_in[0];
    const void*  ei     = d_in[1];
    const float* cheb_w = (const float*)d_in[2];
    const float* cheb_b = (const float*)d_in[3];
    const float* attn_w = (const float*)d_in[4];
    const float* attn_b = (const float*)d_in[5];
    const float* ln_g   = (const float*)d_in[6];
    const float* ln_b   = (const float*)d_in[7];
    float*       out    = (float*)d_out;

    int N = in_sizes[0] / 128;
    int E = in_sizes[1] / 2;
    if (N > NMAX) N = NMAX;
    if (E > EMAX) E = EMAX;

    static int inited = 0;
    static cudaStream_t s2, s3;
    static cudaEvent_t ev[6];
    if (!inited) {
        cudaFuncSetAttribute(k_gemm_all, cudaFuncAttributeMaxDynamicSharedMemorySize,
                             GEMM_SMEM_B);
        int lo, hi;
        cudaDeviceGetStreamPriorityRange(&lo, &hi);
        cudaStreamCreateWithPriority(&s2, cudaStreamNonBlocking, hi);
        cudaStreamCreateWithPriority(&s3, cudaStreamNonBlocking, hi);
        for (int i = 0; i < 6; ++i)
            cudaEventCreateWithFlags(&ev[i], cudaEventDisableTiming);
        inited = 1;
    }

    int tiles2 = (N + 255) / 256;

    // weight prep first on s2 (independent of graph build; overlaps setup ladder)
    k_wprep<<<NMAT, 256, 0, s2>>>(cheb_w);
    cudaEventRecord(ev[0], s2);
    cudaStreamWaitEvent(s3, ev[0], 0);   // s3 GEMMs also need weights

    // graph structure build (stream 0); fused init+detect, fused scan1+dinv
    k_init<<<(N + 255) / 256, 256>>>(ei, E, N);
    k_deg<<<(E + 255) / 256, 256>>>(ei, E, N);
    int nb = (N + 1023) / 1024;
    k_scan1<<<nb, 1024>>>(N);
    k_scan2<<<1, 32>>>(nb, N);
    k_scan3<<<nb, 1024>>>(N);
    k_scatter<<<(E + 255) / 256, 256>>>(ei, E, N);

    int pgrid = (N * 32 + 255) / 256;

    auto gemm = [&](cudaStream_t s, int f, int lo_, int cnt, int accum) {
        k_gemm_all<<<tiles2, 256, GEMM_SMEM_B, s>>>(cheb_b, x, N, f, lo_, cnt, accum);
    };

    // prop 1..4, then release f0 GEMM (s2)
    k_prop<<<pgrid, 256>>>(1, x, 1.0f, 0.0f, N);
    for (int k = 2; k <= 4; ++k)
        k_prop<<<pgrid, 256>>>(k, x, 2.0f, -1.0f, N);
    cudaEventRecord(ev[1], 0);
    cudaStreamWaitEvent(s2, ev[1], 0);
    gemm(s2, 0, 0, 5, 0);

    // prop 5..9, release f1 (s3)
    for (int k = 5; k <= 9; ++k)
        k_prop<<<pgrid, 256>>>(k, x, 2.0f, -1.0f, N);
    cudaEventRecord(ev[2], 0);
    cudaStreamWaitEvent(s3, ev[2], 0);
    gemm(s3, 1, 0, 10, 0);

    // prop 10..14, release f2 (s2) and f3 part 1 (s3) concurrently
    for (int k = 10; k <= 14; ++k)
        k_prop<<<pgrid, 256>>>(k, x, 2.0f, -1.0f, N);
    cudaEventRecord(ev[3], 0);
    cudaStreamWaitEvent(s2, ev[3], 0);
    cudaStreamWaitEvent(s3, ev[3], 0);
    gemm(s2, 2, 0, 15, 0);
    gemm(s3, 3, 0, 15, 0);

    // prop 15..19, release f3 part 2 (s3; accumulates after part 1)
    for (int k = 15; k <= 19; ++k)
        k_prop<<<pgrid, 256>>>(k, x, 2.0f, -1.0f, N);
    cudaEventRecord(ev[4], 0);
    cudaStreamWaitEvent(s3, ev[4], 0);
    gemm(s3, 3, 15, 5, 1);

    // join: final depends on all GEMMs
    cudaEventRecord(ev[0], s2);
    cudaEventRecord(ev[5], s3);
    cudaStreamWaitEvent(0, ev[0], 0);
    cudaStreamWaitEvent(0, ev[5], 0);
    k_final<<<pgrid, 256>>>(attn_w, attn_b, ln_g, ln_b, out, N);
}